// round 17
// baseline (speedup 1.0000x reference)
#include <cuda_runtime.h>
#include <cuda_fp16.h>

#define NB 4
#define NT 2048
#define NC 1024
#define NH 16
#define ND 64
#define NM (NB*NT)      // 8192 rows
#define N_QKV (3*NC)    // 3072

// Scratch (device globals — no allocations allowed)
__device__ __half g_Qh[(size_t)NB*NH*NT*ND];   // [bh][t][d]
__device__ __half g_Kh[(size_t)NB*NH*NT*ND];   // [bh][t][d]
__device__ __half g_Vt[(size_t)NB*NH*ND*NT];   // [bh][d][t]  (transposed)
__device__ __half g_AOh[(size_t)NM*NC];        // [b*t][C]
__device__ __half g_xh[(size_t)NM*NC];
__device__ __half g_Wqh[(size_t)N_QKV*NC];
__device__ __half g_Woh[(size_t)NC*NC];

__device__ __forceinline__ unsigned smem_u32(const void* p) {
    unsigned a;
    asm("{ .reg .u64 t; cvta.to.shared.u64 t, %1; cvt.u32.u64 %0, t; }"
        : "=r"(a) : "l"(p));
    return a;
}
__device__ __forceinline__ void cp_async16(unsigned dst, const void* src) {
    asm volatile("cp.async.cg.shared.global [%0], [%1], 16;" :: "r"(dst), "l"(src));
}
#define CP_COMMIT()  asm volatile("cp.async.commit_group;" ::: "memory")
#define CP_WAIT(n)   asm volatile("cp.async.wait_group %0;" :: "n"(n) : "memory")

#define LDSM4(r0,r1,r2,r3,a) \
    asm volatile("ldmatrix.sync.aligned.m8n8.x4.shared.b16 {%0,%1,%2,%3}, [%4];" \
        : "=r"(r0),"=r"(r1),"=r"(r2),"=r"(r3) : "r"(a))

__device__ __forceinline__ float ex2f(float x) {
    float y; asm("ex2.approx.f32 %0, %1;" : "=f"(y) : "f"(x)); return y;
}
__device__ __forceinline__ unsigned h2u(__half2 h) { return *(unsigned*)&h; }

__device__ __forceinline__ void mma_f16(float c[4], const unsigned a[4], const unsigned b[2]) {
    asm volatile(
        "mma.sync.aligned.m16n8k16.row.col.f32.f16.f16.f32 "
        "{%0,%1,%2,%3}, {%4,%5,%6,%7}, {%8,%9}, {%0,%1,%2,%3};"
        : "+f"(c[0]), "+f"(c[1]), "+f"(c[2]), "+f"(c[3])
        : "r"(a[0]), "r"(a[1]), "r"(a[2]), "r"(a[3]), "r"(b[0]), "r"(b[1]));
}

// ===========================================================================
// fp32 -> fp16 conversion pass
// ===========================================================================
__global__ __launch_bounds__(256) void cvt_h(const float4* __restrict__ in,
                                             uint2* __restrict__ out, int n4)
{
    int i = blockIdx.x * blockDim.x + threadIdx.x;
    const int stride = gridDim.x * blockDim.x;
    for (; i < n4; i += stride) {
        float4 v = in[i];
        out[i] = make_uint2(h2u(__floats2half2_rn(v.x, v.y)),
                            h2u(__floats2half2_rn(v.z, v.w)));
    }
}

// ===========================================================================
// fp16 ldmatrix GEMM: C = A*W^T + bias, K=1024 halves.
// CTA 128x256, warp tile 64x64 (8 warps 2x4): per k0 8 LDSM -> 32 MMA
// (4 MMA/LDSM; smem-per-MAC down ~35% vs 128x128). 4-stage cp.async,
// prefetch distance 3, one barrier per slab, XOR-swizzled 128B rows.
// MODE 0: A=g_xh,  W=g_Wqh; scatter fp16 into g_Qh/g_Kh/g_Vt.
// MODE 1: A=g_AOh, W=g_Woh; fp32 store + bias.
// ===========================================================================
#define BM 128
#define BN 256
#define STAGE_A 16384                          // 128 rows x 128 B
#define STAGE_BYTES 49152                      // A 16KB + B 32KB
#define NSLAB_H (NC/64)                        // 16
#define GEMM_SMEM (4*STAGE_BYTES)              // 196608 B -> 1 CTA/SM

__device__ __forceinline__ void load_slab_h(const __half* __restrict__ A,
                                            const __half* __restrict__ W,
                                            int m0, int n0, int slab, int st,
                                            unsigned sb, int tid)
{
    const unsigned abase = sb + st * STAGE_BYTES;
    const unsigned bbase = abase + STAGE_A;
    const __half* ag = A + (size_t)m0 * NC + slab * 64;
    const __half* wg = W + (size_t)n0 * NC + slab * 64;
    #pragma unroll
    for (int i = 0; i < 4; i++) {              // A: 128 rows x 8 chunks of 16B
        int idx = tid + 256 * i;
        int row = idx >> 3, c16 = idx & 7;
        unsigned sw = (unsigned)((c16 ^ (row & 7)) * 16);
        cp_async16(abase + row * 128 + sw, ag + (size_t)row * NC + c16 * 8);
    }
    #pragma unroll
    for (int i = 0; i < 8; i++) {              // B: 256 rows x 8 chunks of 16B
        int idx = tid + 256 * i;
        int row = idx >> 3, c16 = idx & 7;
        unsigned sw = (unsigned)((c16 ^ (row & 7)) * 16);
        cp_async16(bbase + row * 128 + sw, wg + (size_t)row * NC + c16 * 8);
    }
    CP_COMMIT();
}

template<int MODE>
__global__ __launch_bounds__(256) void gemm_h(const float* __restrict__ bias,
                                              float* __restrict__ Cout)
{
    extern __shared__ char smem[];
    const unsigned sb = smem_u32(smem);
    const int tid  = threadIdx.x;
    const int wid  = tid >> 5, lane = tid & 31;
    const int wm   = wid >> 2;                 // 0..1  (64 rows)
    const int wn   = wid & 3;                  // 0..3  (64 cols)
    const int m0   = blockIdx.y * BM;
    const int n0   = blockIdx.x * BN;
    const __half* A = (MODE == 0) ? g_xh  : g_AOh;
    const __half* W = (MODE == 0) ? g_Wqh : g_Woh;

    const int lr = lane >> 2;
    const int lc = lane & 3;
    const int rsel = lane & 15;
    const int csel = lane >> 4;
    const int bsel = (lane >> 3) & 1;
    const unsigned swb = (unsigned)((lane & 7) * 16);

    unsigned aBase[4], bBase[4];
    #pragma unroll
    for (int mt = 0; mt < 4; mt++)
        aBase[mt] = (unsigned)((wm*64 + mt*16 + rsel) * 128);
    #pragma unroll
    for (int p = 0; p < 4; p++)
        bBase[p] = (unsigned)(STAGE_A + (wn*64 + (2*p + csel)*8 + (lane & 7)) * 128);

    float acc[4][8][4];
    #pragma unroll
    for (int mt = 0; mt < 4; mt++)
        #pragma unroll
        for (int nt = 0; nt < 8; nt++)
            #pragma unroll
            for (int i = 0; i < 4; i++) acc[mt][nt][i] = 0.f;

    load_slab_h(A, W, m0, n0, 0, 0, sb, tid);
    load_slab_h(A, W, m0, n0, 1, 1, sb, tid);
    load_slab_h(A, W, m0, n0, 2, 2, sb, tid);

    for (int i = 0; i < NSLAB_H; i++) {
        const int st = i & 3;
        const int rem = NSLAB_H - 1 - i;
        if (rem >= 2)      CP_WAIT(2);
        else if (rem == 1) CP_WAIT(1);
        else               CP_WAIT(0);
        __syncthreads();

        if (i + 3 < NSLAB_H)
            load_slab_h(A, W, m0, n0, i + 3, (i + 3) & 3, sb, tid);

        const unsigned stg = sb + st * STAGE_BYTES;

        #pragma unroll
        for (int k0 = 0; k0 < 4; k0++) {
            const unsigned offA = ((unsigned)(32*k0 + 16*csel)) ^ swb;
            const unsigned offB = ((unsigned)(32*k0 + 16*bsel)) ^ swb;
            unsigned a[4][4];
            #pragma unroll
            for (int mt = 0; mt < 4; mt++)
                LDSM4(a[mt][0], a[mt][1], a[mt][2], a[mt][3],
                      stg + aBase[mt] + offA);
            #pragma unroll
            for (int p = 0; p < 4; p++) {
                unsigned b[4];
                LDSM4(b[0], b[1], b[2], b[3], stg + bBase[p] + offB);
                #pragma unroll
                for (int mt = 0; mt < 4; mt++) {
                    mma_f16(acc[mt][2*p    ], a[mt], b);
                    mma_f16(acc[mt][2*p + 1], a[mt], b + 2);
                }
            }
        }
    }

    #pragma unroll
    for (int mt = 0; mt < 4; mt++) {
        const int row = m0 + wm*64 + mt*16 + lr;
        #pragma unroll
        for (int nt = 0; nt < 8; nt++) {
            const int col = n0 + wn*64 + nt*8 + 2*lc;
            const float b0 = bias[col], b1 = bias[col + 1];
            const float v00 = acc[mt][nt][0] + b0, v01 = acc[mt][nt][1] + b1;
            const float v10 = acc[mt][nt][2] + b0, v11 = acc[mt][nt][3] + b1;
            if (MODE == 0) {
                const int sel = col >> 10;
                const int h   = (col & 1023) >> 6;
                const int d0  = col & 63;
                const int bb  = row >> 11;
                const int t   = row & (NT - 1);
                const size_t bh = (size_t)(bb * NH + h);
                if (sel == 2) {
                    __half* p = g_Vt + (bh * ND + d0) * NT + t;
                    p[0]      = __float2half_rn(v00);
                    p[NT]     = __float2half_rn(v01);
                    p[8]      = __float2half_rn(v10);
                    p[NT + 8] = __float2half_rn(v11);
                } else {
                    __half* dst = (sel == 0) ? g_Qh : g_Kh;
                    __half* p = dst + (bh * NT + t) * ND + d0;
                    *(unsigned*)p          = h2u(__floats2half2_rn(v00, v01));
                    *(unsigned*)(p + 8*ND) = h2u(__floats2half2_rn(v10, v11));
                }
            } else {
                float* p = Cout + (size_t)row * NC + col;
                *(float2*)p          = make_float2(v00, v01);
                *(float2*)(p + 8*NC) = make_float2(v10, v11);
            }
        }
    }
}

// ===========================================================================
// Flash attention (unchanged from round 16): fp16 ldmatrix, q-tile 128,
// register-resident P (S-accum layout == PV A-operand layout).
// ===========================================================================
#define AK_OFF 0
#define AV_OFF 16384
#define AQP_OFF 32768
#define ATTN_SMEM 49152

__device__ __forceinline__ void attn_load_kv(const __half* Kt, const __half* VtT,
                                             unsigned kb, unsigned vb, int tid)
{
    #pragma unroll
    for (int i = 0; i < 2; i++) {
        int idx = tid + 256*i;
        int row = idx >> 3, c16 = idx & 7;
        unsigned sw = (unsigned)((c16 ^ (row & 7)) * 16);
        cp_async16(kb + row*128 + sw, Kt + (size_t)row*ND + c16*8);
    }
    #pragma unroll
    for (int i = 0; i < 2; i++) {
        int idx = tid + 256*i;
        int row = idx >> 3, c16 = idx & 7;
        unsigned sw = (unsigned)((c16 ^ (row & 7)) * 16);
        cp_async16(vb + row*128 + sw, VtT + (size_t)row*NT + c16*8);
    }
}

__global__ __launch_bounds__(256) void attn_mma()
{
    extern __shared__ char smc[];
    const unsigned sb = smem_u32(smc);
    const int tid = threadIdx.x, wid = tid >> 5, lane = tid & 31;
    const int lr = lane >> 2, lc = lane & 3;
    const int rsel = lane & 15;
    const int csel = lane >> 4;
    const int bsel = (lane >> 3) & 1;
    const unsigned swb = (unsigned)((lane & 7) * 16);
    const int qt = (int)gridDim.x - 1 - (int)blockIdx.x;
    const int bh = blockIdx.y;
    const int q0 = qt * 128;
    const int nkt = 2*qt + 2;

    const __half* Qp  = g_Qh + (size_t)bh * NT * ND;
    const __half* Kp  = g_Kh + (size_t)bh * NT * ND;
    const __half* VtT = g_Vt + (size_t)bh * ND * NT;

    unsigned kvB[4];
    #pragma unroll
    for (int p = 0; p < 4; p++)
        kvB[p] = (unsigned)(((2*p + csel)*8 + (lane & 7)) * 128);
    const unsigned qpA = (unsigned)((wid*16 + rsel) * 128);

    #pragma unroll
    for (int i = 0; i < 4; i++) {
        int idx = tid + 256*i;
        int row = idx >> 3, c16 = idx & 7;
        unsigned sw = (unsigned)((c16 ^ (row & 7)) * 16);
        cp_async16(sb + AQP_OFF + row*128 + sw, Qp + (size_t)(q0 + row)*ND + c16*8);
    }
    attn_load_kv(Kp, VtT, sb + AK_OFF, sb + AV_OFF, tid);
    CP_COMMIT();
    CP_WAIT(0);
    __syncthreads();

    const float qsc = 0.125f * 1.44269504f;
    unsigned qa[4][4];
    #pragma unroll
    for (int k0 = 0; k0 < 4; k0++) {
        const unsigned offA = ((unsigned)(32*k0 + 16*csel)) ^ swb;
        unsigned raw[4];
        LDSM4(raw[0], raw[1], raw[2], raw[3], sb + AQP_OFF + qpA + offA);
        #pragma unroll
        for (int j = 0; j < 4; j++) {
            float2 f = __half22float2(*(__half2*)&raw[j]);
            qa[k0][j] = h2u(__floats2half2_rn(f.x * qsc, f.y * qsc));
        }
    }

    float m0 = -1e30f, m1 = -1e30f, l0 = 0.f, l1 = 0.f;
    float o[8][4];
    #pragma unroll
    for (int nt = 0; nt < 8; nt++) { o[nt][0]=o[nt][1]=o[nt][2]=o[nt][3]=0.f; }

    for (int kt = 0; kt < nkt; kt++) {
        const int st = kt & 1;
        CP_WAIT(0);
        __syncthreads();
        if (kt + 1 < nkt) {
            attn_load_kv(Kp + (size_t)(kt+1)*64*ND, VtT + (kt+1)*64,
                         sb + AK_OFF + (st^1)*8192,
                         sb + AV_OFF + (st^1)*8192, tid);
            CP_COMMIT();
        }

        const unsigned kstg = sb + AK_OFF + st*8192;
        const unsigned vstg = sb + AV_OFF + st*8192;

        float s[8][4];
        #pragma unroll
        for (int nt = 0; nt < 8; nt++) { s[nt][0]=s[nt][1]=s[nt][2]=s[nt][3]=0.f; }
        #pragma unroll
        for (int k0 = 0; k0 < 4; k0++) {
            const unsigned offB = ((unsigned)(32*k0 + 16*bsel)) ^ swb;
            #pragma unroll
            for (int p = 0; p < 4; p++) {
                unsigned b[4];
                LDSM4(b[0], b[1], b[2], b[3], kstg + kvB[p] + offB);
                mma_f16(s[2*p    ], qa[k0], b);
                mma_f16(s[2*p + 1], qa[k0], b + 2);
            }
        }

        if (kt >= 2*qt) {
            const int r0g = q0 + wid*16 + lr;
            #pragma unroll
            for (int nt = 0; nt < 8; nt++) {
                const int c0 = kt*64 + nt*8 + 2*lc;
                if (c0     > r0g    ) s[nt][0] = -1e30f;
                if (c0 + 1 > r0g    ) s[nt][1] = -1e30f;
                if (c0     > r0g + 8) s[nt][2] = -1e30f;
                if (c0 + 1 > r0g + 8) s[nt][3] = -1e30f;
            }
        }

        float tm0 = -1e30f, tm1 = -1e30f;
        #pragma unroll
        for (int nt = 0; nt < 8; nt++) {
            tm0 = fmaxf(tm0, fmaxf(s[nt][0], s[nt][1]));
            tm1 = fmaxf(tm1, fmaxf(s[nt][2], s[nt][3]));
        }
        tm0 = fmaxf(tm0, __shfl_xor_sync(0xffffffffu, tm0, 1));
        tm0 = fmaxf(tm0, __shfl_xor_sync(0xffffffffu, tm0, 2));
        tm1 = fmaxf(tm1, __shfl_xor_sync(0xffffffffu, tm1, 1));
        tm1 = fmaxf(tm1, __shfl_xor_sync(0xffffffffu, tm1, 2));

        const float mn0 = fmaxf(m0, tm0), mn1 = fmaxf(m1, tm1);
        const float sc0 = ex2f(m0 - mn0), sc1 = ex2f(m1 - mn1);
        m0 = mn0; m1 = mn1;

        unsigned pa[4][4];
        float rs0 = 0.f, rs1 = 0.f;
        #pragma unroll
        for (int nt = 0; nt < 8; nt++) {
            float p0 = ex2f(s[nt][0] - mn0);
            float p1 = ex2f(s[nt][1] - mn0);
            float p2 = ex2f(s[nt][2] - mn1);
            float p3 = ex2f(s[nt][3] - mn1);
            rs0 += p0 + p1;
            rs1 += p2 + p3;
            const int k0 = nt >> 1;
            if ((nt & 1) == 0) {
                pa[k0][0] = h2u(__floats2half2_rn(p0, p1));
                pa[k0][1] = h2u(__floats2half2_rn(p2, p3));
            } else {
                pa[k0][2] = h2u(__floats2half2_rn(p0, p1));
                pa[k0][3] = h2u(__floats2half2_rn(p2, p3));
            }
        }
        rs0 += __shfl_xor_sync(0xffffffffu, rs0, 1);
        rs0 += __shfl_xor_sync(0xffffffffu, rs0, 2);
        rs1 += __shfl_xor_sync(0xffffffffu, rs1, 1);
        rs1 += __shfl_xor_sync(0xffffffffu, rs1, 2);
        l0 = l0*sc0 + rs0;
        l1 = l1*sc1 + rs1;
        #pragma unroll
        for (int nt = 0; nt < 8; nt++) {
            o[nt][0] *= sc0; o[nt][1] *= sc0;
            o[nt][2] *= sc1; o[nt][3] *= sc1;
        }

        #pragma unroll
        for (int k0 = 0; k0 < 4; k0++) {
            const unsigned offB = ((unsigned)(32*k0 + 16*bsel)) ^ swb;
            #pragma unroll
            for (int p = 0; p < 4; p++) {
                unsigned b[4];
                LDSM4(b[0], b[1], b[2], b[3], vstg + kvB[p] + offB);
                mma_f16(o[2*p    ], pa[k0], b);
                mma_f16(o[2*p + 1], pa[k0], b + 2);
            }
        }
    }

    const float inv0 = 1.f / l0, inv1 = 1.f / l1;
    const int b = bh >> 4, h = bh & 15;
    const int r0 = q0 + wid*16 + lr, r1 = r0 + 8;
    unsigned* ao0 = (unsigned*)(g_AOh + ((size_t)(b*NT + r0))*NC + h*ND);
    unsigned* ao1 = (unsigned*)(g_AOh + ((size_t)(b*NT + r1))*NC + h*ND);
    #pragma unroll
    for (int nt = 0; nt < 8; nt++) {
        ao0[nt*4 + lc] = h2u(__floats2half2_rn(o[nt][0]*inv0, o[nt][1]*inv0));
        ao1[nt*4 + lc] = h2u(__floats2half2_rn(o[nt][2]*inv1, o[nt][3]*inv1));
    }
}

// ---------------------------------------------------------------------------
extern "C" void kernel_launch(void* const* d_in, const int* in_sizes, int n_in,
                              void* d_out, int out_size)
{
    const float* x     = (const float*)d_in[0];
    const float* Wqkv  = (const float*)d_in[1];
    const float* bqkv  = (const float*)d_in[2];
    const float* Wout  = (const float*)d_in[3];
    const float* bout  = (const float*)d_in[4];
    float* out = (float*)d_out;

    static int cfg_done = 0;
    if (!cfg_done) {
        cudaFuncSetAttribute(gemm_h<0>, cudaFuncAttributeMaxDynamicSharedMemorySize, GEMM_SMEM);
        cudaFuncSetAttribute(gemm_h<1>, cudaFuncAttributeMaxDynamicSharedMemorySize, GEMM_SMEM);
        cudaFuncSetAttribute(attn_mma,  cudaFuncAttributeMaxDynamicSharedMemorySize, ATTN_SMEM);
        cfg_done = 1;
    }

    void *xh, *wqh, *woh;
    cudaGetSymbolAddress(&xh,  g_xh);
    cudaGetSymbolAddress(&wqh, g_Wqh);
    cudaGetSymbolAddress(&woh, g_Woh);

    cvt_h<<<1184, 256>>>((const float4*)x,    (uint2*)xh,  NM*NC/4);
    cvt_h<<<1184, 256>>>((const float4*)Wqkv, (uint2*)wqh, N_QKV*NC/4);
    cvt_h<<<296,  256>>>((const float4*)Wout, (uint2*)woh, NC*NC/4);

    gemm_h<0><<<dim3(N_QKV/BN, NM/BM), 256, GEMM_SMEM>>>(bqkv, nullptr);
    attn_mma<<<dim3(NT/128, NB*NH), 256, ATTN_SMEM>>>();
    gemm_h<1><<<dim3(NC/BN, NM/BM), 256, GEMM_SMEM>>>(bout, out);
}